// round 11
// baseline (speedup 1.0000x reference)
#include <cuda_runtime.h>
#include <cstdint>
#include <cstddef>

#define DIMC 256
#define NH 8
#define HD 32
#define NQ 4096
#define NU 1024
#define BATCH 2

#define THREEFRY_PARTITIONABLE 1

typedef unsigned long long ull;

// ---------------- scratch (device globals; no allocation) ----------------
__device__ float g_q   [BATCH * DIMC * NQ];      // q channels  [b][c][n]
__device__ float g_kvu [BATCH * 2 * DIMC * NU];  // kv upper    [b][c][m]
__device__ float g_kvT [BATCH * NH * NU * 64];   // transposed  [b][h][m][d64] (K:0-31, V:32-63)
__device__ float g_fkv [BATCH * 2 * DIMC * NQ];  // fine kv     [b][c][n]
__device__ float g_qm  [BATCH * DIMC];
__device__ float g_gs  [BATCH * NH * NU];
__device__ int   g_idx [BATCH * NH * 16];
__device__ float g_out [BATCH * DIMC * NQ];
__device__ float g_vpe [BATCH * DIMC * NU];

// ---------------- f32x2 packed helpers ----------------
__device__ __forceinline__ ull ffma2(ull a, ull b, ull c) {
    ull d; asm("fma.rn.f32x2 %0, %1, %2, %3;" : "=l"(d) : "l"(a), "l"(b), "l"(c)); return d;
}
__device__ __forceinline__ ull fmul2(ull a, ull b) {
    ull d; asm("mul.rn.f32x2 %0, %1, %2;" : "=l"(d) : "l"(a), "l"(b)); return d;
}
__device__ __forceinline__ ull pack2(float lo, float hi) {
    ull r; asm("mov.b64 %0, {%1, %2};" : "=l"(r) : "f"(lo), "f"(hi)); return r;
}
__device__ __forceinline__ float2 unpack2(ull v) {
    float2 f; asm("mov.b64 {%0, %1}, %2;" : "=f"(f.x), "=f"(f.y) : "l"(v)); return f;
}

// ---------------- fast exp2 (scalar, clamped) ----------------
__device__ __forceinline__ float fexp2(float x) {
    x = fmaxf(fminf(x, 126.0f), -120.0f);
    float z = x + 12582912.0f;
    int   e = __float_as_int(z) - 0x4B400000;
    float f = x - (z - 12582912.0f);
    float p = fmaf(f, 1.3333558146e-3f, 9.6181291918e-3f);
    p = fmaf(f, p, 5.5504108664e-2f);
    p = fmaf(f, p, 2.4022650696e-1f);
    p = fmaf(f, p, 6.9314718056e-1f);
    p = fmaf(f, p, 1.0f);
    return p * __int_as_float((e + 127) << 23);
}

// packed exp2 of two scores (inputs bounded, no clamp needed)
__device__ __forceinline__ ull fexp2_2(float x0, float x1) {
    float z0 = x0 + 12582912.0f, z1 = x1 + 12582912.0f;
    int e0 = __float_as_int(z0) - 0x4B400000;
    int e1 = __float_as_int(z1) - 0x4B400000;
    float f0 = x0 - (z0 - 12582912.0f);
    float f1 = x1 - (z1 - 12582912.0f);
    ull f2 = pack2(f0, f1);
    ull p  = pack2(1.3333558146e-3f, 1.3333558146e-3f);
    p = ffma2(f2, p, pack2(9.6181291918e-3f, 9.6181291918e-3f));
    p = ffma2(f2, p, pack2(5.5504108664e-2f, 5.5504108664e-2f));
    p = ffma2(f2, p, pack2(2.4022650696e-1f, 2.4022650696e-1f));
    p = ffma2(f2, p, pack2(6.9314718056e-1f, 6.9314718056e-1f));
    p = ffma2(f2, p, pack2(1.0f, 1.0f));
    ull sc = pack2(__int_as_float((e0 + 127) << 23), __int_as_float((e1 + 127) << 23));
    return fmul2(p, sc);
}

// ---------------- threefry2x32 (key = (0, 42)) ----------------
__device__ __forceinline__ uint32_t rotl32(uint32_t v, int n) { return (v << n) | (v >> (32 - n)); }

__device__ __forceinline__ void tf2x32(uint32_t c0, uint32_t c1, uint32_t& o0, uint32_t& o1) {
    const uint32_t k0 = 0u, k1 = 42u, k2 = 0u ^ 42u ^ 0x1BD11BDAu;
    uint32_t x0 = c0 + k0, x1 = c1 + k1;
#define TFR(r) { x0 += x1; x1 = rotl32(x1, r); x1 ^= x0; }
    TFR(13) TFR(15) TFR(26) TFR(6)
    x0 += k1; x1 += k2 + 1u;
    TFR(17) TFR(29) TFR(16) TFR(24)
    x0 += k2; x1 += k0 + 2u;
    TFR(13) TFR(15) TFR(26) TFR(6)
    x0 += k0; x1 += k1 + 3u;
    TFR(17) TFR(29) TFR(16) TFR(24)
    x0 += k1; x1 += k2 + 4u;
    TFR(13) TFR(15) TFR(26) TFR(6)
    x0 += k2; x1 += k0 + 5u;
#undef TFR
    o0 = x0; o1 = x1;
}

// ---------------- GEMM (f32x2): C[M,N] = W[M,256] @ X[256,N] + bias ----------------
__global__ __launch_bounds__(256) void gemm128(const float* __restrict__ W,
                                               const float* __restrict__ X,
                                               const float* __restrict__ bias,
                                               float* __restrict__ C, int M, int N) {
    const int K = DIMC;
    int b = blockIdx.z;
    X += (size_t)b * K * N;
    C += (size_t)b * M * N;
    __shared__ float Ws[8][132];
    __shared__ float Xs[8][128];
    int tid = threadIdx.x;
    int tx = tid & 15, ty = tid >> 4;
    int bm = blockIdx.y * 128, bn = blockIdx.x * 128;

    ull acc2[4][8];
#pragma unroll
    for (int i = 0; i < 4; i++)
#pragma unroll
        for (int j = 0; j < 8; j++) acc2[i][j] = 0ull;

    int wk = tid & 7, wm = tid >> 3;
    int xk = tid >> 7, xn = tid & 127;

    for (int k0 = 0; k0 < K; k0 += 8) {
#pragma unroll
        for (int p = 0; p < 4; p++)
            Ws[wk][wm + p * 32] = W[(size_t)(bm + wm + p * 32) * K + k0 + wk];
#pragma unroll
        for (int p = 0; p < 4; p++)
            Xs[xk + p * 2][xn] = X[(size_t)(k0 + xk + p * 2) * N + bn + xn];
        __syncthreads();
#pragma unroll
        for (int k = 0; k < 8; k++) {
            ull a2[4];
            {
                ulonglong2 t0 = *(const ulonglong2*)&Ws[k][ty * 4];
                ulonglong2 t1 = *(const ulonglong2*)&Ws[k][64 + ty * 4];
                a2[0] = t0.x; a2[1] = t0.y; a2[2] = t1.x; a2[3] = t1.y;
            }
            float bb[8];
            *(float4*)&bb[0] = *(const float4*)&Xs[k][tx * 4];
            *(float4*)&bb[4] = *(const float4*)&Xs[k][64 + tx * 4];
#pragma unroll
            for (int j = 0; j < 8; j++) {
                ull b2 = pack2(bb[j], bb[j]);
#pragma unroll
                for (int i = 0; i < 4; i++) acc2[i][j] = ffma2(a2[i], b2, acc2[i][j]);
            }
        }
        __syncthreads();
    }
#pragma unroll
    for (int i = 0; i < 8; i++) {
        int loc  = (i < 4) ? i : (i - 4);
        int i2   = ((i < 4) ? 0 : 2) + (loc >> 1);
        int half = loc & 1;
        int m = bm + ((i < 4) ? 0 : 64) + ty * 4 + loc;
        float bv = bias[m];
        float v[8];
#pragma unroll
        for (int j = 0; j < 8; j++) {
            float2 u = unpack2(acc2[i2][j]);
            v[j] = (half ? u.y : u.x) + bv;
        }
        *(float4*)&C[(size_t)m * N + bn + tx * 4]      = make_float4(v[0], v[1], v[2], v[3]);
        *(float4*)&C[(size_t)m * N + bn + 64 + tx * 4] = make_float4(v[4], v[5], v[6], v[7]);
    }
}

// ---------------- transpose kv upper: [b][c][m] -> [b][h][m][d64] ----------------
__global__ __launch_bounds__(256) void tr_k() {
    int bh = blockIdx.x >> 4, tile = blockIdx.x & 15;
    int b = bh >> 3, h = bh & 7;
    int m0 = tile * 64;
    __shared__ float s[64][65];
    int t = threadIdx.x;
    const float* src = g_kvu + ((size_t)b * 512 + h * 64) * NU + m0;
#pragma unroll
    for (int i = 0; i < 16; i++) {
        int idx = i * 256 + t;
        int dd = idx >> 6, mm = idx & 63;
        s[dd][mm] = src[(size_t)dd * NU + mm];
    }
    __syncthreads();
    float* dst = g_kvT + ((size_t)bh * NU + m0) * 64;
#pragma unroll
    for (int i = 0; i < 16; i++) {
        int idx = i * 256 + t;
        int mm = idx >> 6, dd = idx & 63;
        dst[mm * 64 + dd] = s[dd][mm];
    }
}

// ---------------- mean over n of q channels (float4) ----------------
__global__ void qmean_k() {
    int b = blockIdx.x >> 8, c = blockIdx.x & 255;
    const float4* p = (const float4*)(g_q + ((size_t)b * DIMC + c) * NQ);
    float s = 0.f;
    for (int n = threadIdx.x; n < 1024; n += 256) {
        float4 v = p[n];
        s += (v.x + v.y) + (v.z + v.w);
    }
    __shared__ float sh[8];
    for (int o = 16; o; o >>= 1) s += __shfl_down_sync(0xffffffffu, s, o);
    if ((threadIdx.x & 31) == 0) sh[threadIdx.x >> 5] = s;
    __syncthreads();
    if (threadIdx.x == 0) {
        float t = 0.f;
#pragma unroll
        for (int i = 0; i < 8; i++) t += sh[i];
        g_qm[b * DIMC + c] = t * (1.0f / NQ);
    }
}

// ---------------- global scores + gumbel (reads transposed K) ----------------
__global__ void gs_k() {
    int j = blockIdx.x * 128 + threadIdx.x;
    int b = j >> 13, r = j & 8191, h = r >> 10, m = r & 1023;
    const float4* qm = (const float4*)(g_qm + b * DIMC + h * HD);
    const float4* kT = (const float4*)(g_kvT + ((size_t)(b * NH + h) * NU + m) * 64);
    float s = 0.f;
#pragma unroll
    for (int i = 0; i < 8; i++) {
        float4 qv = qm[i], kv = kT[i];
        s += qv.x * kv.x + qv.y * kv.y + qv.z * kv.z + qv.w * kv.w;
    }

    uint32_t bits;
#if THREEFRY_PARTITIONABLE
    { uint32_t o0, o1; tf2x32(0u, (uint32_t)j, o0, o1); bits = o0 ^ o1; }
#else
    { uint32_t o0, o1;
      if (j < 8192) { tf2x32((uint32_t)j, (uint32_t)(j + 8192), o0, o1); bits = o0; }
      else          { tf2x32((uint32_t)(j - 8192), (uint32_t)j, o0, o1); bits = o1; } }
#endif
    float f = __uint_as_float((bits >> 9) | 0x3f800000u) - 1.0f;
    const float TINY = 1.1754943508222875e-38f;
    float u = fmaxf(TINY, f + TINY);
    float gum = -logf(-logf(u));
    g_gs[j] = s * 0.17677669529663687f + gum;
}

// ---------------- top-4 per (b,h) + 2x2 expansion ----------------
__global__ void topk_k() {
    int bh = blockIdx.x;
    __shared__ float sv[NU];
    __shared__ float rv[256];
    __shared__ int   ri[256];
    __shared__ int   chosen[4];
    int t = threadIdx.x;
    for (int i = t; i < NU; i += 256) sv[i] = g_gs[bh * NU + i];
    __syncthreads();
    for (int rnd = 0; rnd < 4; rnd++) {
        float bestv = -1e30f; int besti = NU;
        for (int i = t; i < NU; i += 256) {
            float v = sv[i];
            if (v > bestv) { bestv = v; besti = i; }
        }
        rv[t] = bestv; ri[t] = besti;
        __syncthreads();
        for (int o = 128; o; o >>= 1) {
            if (t < o) {
                float v2 = rv[t + o]; int i2 = ri[t + o];
                if (v2 > rv[t] || (v2 == rv[t] && i2 < ri[t])) { rv[t] = v2; ri[t] = i2; }
            }
            __syncthreads();
        }
        if (t == 0) { chosen[rnd] = ri[0]; sv[ri[0]] = -1e30f; }
        __syncthreads();
    }
    if (t < 16) {
        int g = t >> 2, kk = t & 3;
        int dh = g >> 1, dw = g & 1;
        int ti = chosen[kk];
        int hi = (ti >> 5) * 2, wi = (ti & 31) * 2;
        g_idx[bh * 16 + t] = (hi + dh) * 64 + (wi + dw);
    }
}

// ---------------- fused attention: 1 query/thread, LDS.128 K/V (d-contiguous tile) ----------------
__global__ __launch_bounds__(128) void attn_k(const float* __restrict__ Wg,
                                              const float* __restrict__ bg) {
    __shared__ float KVs[128][64];   // [m][d64]: K cols 0-31, V cols 32-63 (32 KB)
    __shared__ ull FKp[16][16];
    __shared__ ull FVp[16][16];
    __shared__ ull Wgp[32][32];
    __shared__ float bgs[32];

    int bh = blockIdx.y, b = bh >> 3, h = bh & 7;
    int t = threadIdx.x;
    int n = blockIdx.x * 128 + t;
    const float SCL = 0.17677669529663687f * 1.4426950408889634f;

    for (int e = t; e < 1024; e += 128) ((ull*)Wgp)[e] = ((const ull*)Wg)[e];
    if (t < 32) bgs[t] = bg[t];
    {
        const int* idxp = g_idx + bh * 16;
        const float* fb = g_fkv + ((size_t)b * 512 + h * 64) * NQ;
        for (int e = t; e < 256; e += 128) {
            int j = e >> 4, p = e & 15;
            int nn = idxp[j];
            FKp[j][p] = pack2(fb[(size_t)(2 * p) * NQ + nn],      fb[(size_t)(2 * p + 1) * NQ + nn]);
            FVp[j][p] = pack2(fb[(size_t)(32 + 2 * p) * NQ + nn], fb[(size_t)(33 + 2 * p) * NQ + nn]);
        }
    }

    // load + pre-scale query (packed pairs of adjacent d)
    ull q2[16];
    {
        const float* qb = g_q + ((size_t)b * DIMC + h * HD) * NQ;
#pragma unroll
        for (int p = 0; p < 16; p++)
            q2[p] = pack2(qb[(size_t)(2 * p) * NQ + n] * SCL,
                          qb[(size_t)(2 * p + 1) * NQ + n] * SCL);
    }

    ull acc2[16];
#pragma unroll
    for (int p = 0; p < 16; p++) acc2[p] = 0ull;
    float esum = 0.f;

    const float* kvT = g_kvT + (size_t)bh * NU * 64;

    for (int m0 = 0; m0 < NU; m0 += 128) {
        __syncthreads();
        {
            const float4* src = (const float4*)(kvT + (size_t)m0 * 64);
            float4* dst = (float4*)KVs;
#pragma unroll
            for (int i = 0; i < 16; i++) dst[i * 128 + t] = src[i * 128 + t];
        }
        __syncthreads();
#pragma unroll 1
        for (int m = 0; m < 128; m += 2) {
            float s0, s1;
            {
                ull x0 = 0ull, x1 = 0ull, y0 = 0ull, y1 = 0ull;
                const ulonglong2* k0 = (const ulonglong2*)&KVs[m][0];
                const ulonglong2* k1 = (const ulonglong2*)&KVs[m + 1][0];
#pragma unroll
                for (int j = 0; j < 8; j++) {
                    ulonglong2 ka = k0[j];
                    ulonglong2 kb = k1[j];
                    x0 = ffma2(q2[2 * j],     ka.x, x0);
                    x1 = ffma2(q2[2 * j + 1], ka.y, x1);
                    y0 = ffma2(q2[2 * j],     kb.x, y0);
                    y1 = ffma2(q2[2 * j + 1], kb.y, y1);
                }
                float2 u0 = unpack2(x0), u1 = unpack2(x1);
                float2 v0 = unpack2(y0), v1 = unpack2(y1);
                s0 = (u0.x + u0.y) + (u1.x + u1.y);
                s1 = (v0.x + v0.y) + (v1.x + v1.y);
            }
            float2 ee = unpack2(fexp2_2(s0, s1));
            esum += ee.x + ee.y;
            ull e0 = pack2(ee.x, ee.x), e1 = pack2(ee.y, ee.y);
            {
                const ulonglong2* v0p = (const ulonglong2*)&KVs[m][32];
                const ulonglong2* v1p = (const ulonglong2*)&KVs[m + 1][32];
#pragma unroll
                for (int j = 0; j < 8; j++) {
                    ulonglong2 va = v0p[j];
                    acc2[2 * j]     = ffma2(e0, va.x, acc2[2 * j]);
                    acc2[2 * j + 1] = ffma2(e0, va.y, acc2[2 * j + 1]);
                    ulonglong2 vb = v1p[j];
                    acc2[2 * j]     = ffma2(e1, vb.x, acc2[2 * j]);
                    acc2[2 * j + 1] = ffma2(e1, vb.y, acc2[2 * j + 1]);
                }
            }
        }
    }

    // fine attention weights (uses q2, before it is overwritten)
    float fe[16]; float fsum = 0.f;
#pragma unroll
    for (int j = 0; j < 16; j++) {
        ull s2 = 0ull;
#pragma unroll
        for (int p = 0; p < 16; p++) s2 = ffma2(q2[p], FKp[j][p], s2);
        float2 u = unpack2(s2);
        float e1 = fexp2(u.x + u.y);
        fe[j] = e1; fsum += e1;
    }
    ull invf2, invc2;
    { float invf = 1.0f / fsum, invc = 1.0f / esum;
      invf2 = pack2(invf, invf); invc2 = pack2(invc, invc); }

    // refined output overwrites q2; coarse scaled in place in acc2
#pragma unroll
    for (int p = 0; p < 16; p++) {
        ull r = 0ull;
#pragma unroll
        for (int j = 0; j < 16; j++) r = ffma2(pack2(fe[j], fe[j]), FVp[j][p], r);
        q2[p]   = fmul2(r, invf2);
        acc2[p] = fmul2(acc2[p], invc2);
    }

    // gate + output
    float* outb = g_out + ((size_t)b * DIMC + h * HD) * NQ + n;
#pragma unroll
    for (int d = 0; d < 32; d++) {
        ull g2 = 0ull;
#pragma unroll
        for (int p = 0; p < 16; p++) {
            g2 = ffma2(acc2[p], Wgp[d][p],      g2);
            g2 = ffma2(q2[p],   Wgp[d][16 + p], g2);
        }
        float2 u = unpack2(g2);
        float s = u.x + u.y + bgs[d];
        float gate = 1.0f / (1.0f + fexp2(-s * 1.4426950408889634f));
        float2 cc = unpack2(acc2[d >> 1]);
        float2 rr = unpack2(q2[d >> 1]);
        float cd = (d & 1) ? cc.y : cc.x;
        float rd = (d & 1) ? rr.y : rr.x;
        outb[(size_t)d * NQ] = cd + gate * (rd - cd);
    }
}

// ---------------- depthwise 7x7 conv on v (32x32 grid) ----------------
__global__ void pe_conv_k(const float* __restrict__ Wpe, const float* __restrict__ bpe) {
    int gid = blockIdx.x * 128 + threadIdx.x;
    int p = gid & 1023, c = (gid >> 10) & 255, b = gid >> 18;
    int y = p >> 5, x = p & 31;
    int h = c >> 5, d = c & 31;
    const float* vsrc = g_kvu + ((size_t)b * 512 + h * 64 + 32 + d) * NU;
    const float* w = Wpe + c * 49;
    float s = bpe[c];
#pragma unroll
    for (int ky = 0; ky < 7; ky++) {
        int iy = y + ky - 3;
        if ((unsigned)iy < 32u) {
#pragma unroll
            for (int kx = 0; kx < 7; kx++) {
                int ix = x + kx - 3;
                if ((unsigned)ix < 32u) s = fmaf(vsrc[iy * 32 + ix], w[ky * 7 + kx], s);
            }
        }
    }
    g_vpe[gid] = s;
}

// ---------------- bilinear 2x upsample + add ----------------
__global__ void upadd_k() {
    int gid = blockIdx.x * 256 + threadIdx.x;
    int n = gid & 4095, c = (gid >> 12) & 255, b = gid >> 20;
    int y = n >> 6, x = n & 63;
    float fy = (y + 0.5f) * 0.5f - 0.5f;
    float fx = (x + 0.5f) * 0.5f - 0.5f;
    float yf = floorf(fy), xf = floorf(fx);
    float ty = fy - yf, tx = fx - xf;
    int y0 = max(0, min(31, (int)yf)),     y1 = max(0, min(31, (int)yf + 1));
    int x0 = max(0, min(31, (int)xf)),     x1 = max(0, min(31, (int)xf + 1));
    const float* src = g_vpe + ((size_t)b * 256 + c) * NU;
    float v = (1.f - ty) * ((1.f - tx) * src[y0 * 32 + x0] + tx * src[y0 * 32 + x1])
            +        ty  * ((1.f - tx) * src[y1 * 32 + x0] + tx * src[y1 * 32 + x1]);
    g_out[gid] += v;
}

// ---------------- launch ----------------
extern "C" void kernel_launch(void* const* d_in, const int* in_sizes, int n_in,
                              void* d_out, int out_size) {
    const float* x     = (const float*)d_in[0];
    const float* uf    = (const float*)d_in[1];
    const float* Wq    = (const float*)d_in[2];
    const float* bq    = (const float*)d_in[3];
    const float* Wkv   = (const float*)d_in[4];
    const float* bkv   = (const float*)d_in[5];
    const float* Wproj = (const float*)d_in[6];
    const float* bproj = (const float*)d_in[7];
    const float* Wpe   = (const float*)d_in[8];
    const float* bpe   = (const float*)d_in[9];
    const float* Wg    = (const float*)d_in[10];
    const float* bg    = (const float*)d_in[11];
    float* out = (float*)d_out;

    float *pq, *pkvu, *pfkv, *pout;
    cudaGetSymbolAddress((void**)&pq,   g_q);
    cudaGetSymbolAddress((void**)&pkvu, g_kvu);
    cudaGetSymbolAddress((void**)&pfkv, g_fkv);
    cudaGetSymbolAddress((void**)&pout, g_out);

    gemm128<<<dim3(32, 2, 2), 256>>>(Wq,  x,  bq,  pq,   256, 4096);
    gemm128<<<dim3(8,  4, 2), 256>>>(Wkv, uf, bkv, pkvu, 512, 1024);
    gemm128<<<dim3(32, 4, 2), 256>>>(Wkv, x,  bkv, pfkv, 512, 4096);
    tr_k<<<256, 256>>>();
    qmean_k<<<512, 256>>>();
    gs_k<<<128, 128>>>();
    topk_k<<<16, 256>>>();
    attn_k<<<dim3(32, 16), 128>>>(Wg, bg);
    pe_conv_k<<<4096, 128>>>(Wpe, bpe);
    upadd_k<<<8192, 256>>>();
    gemm128<<<dim3(32, 2, 2), 256>>>(Wproj, pout, bproj, out, 256, 4096);
}

// round 15
// speedup vs baseline: 1.5250x; 1.5250x over previous
#include <cuda_runtime.h>
#include <cstdint>
#include <cstddef>

#define DIMC 256
#define NH 8
#define HD 32
#define NQ 4096
#define NU 1024
#define BATCH 2

#define THREEFRY_PARTITIONABLE 1

typedef unsigned long long ull;

// ---------------- scratch (device globals; no allocation) ----------------
__device__ float g_q   [BATCH * DIMC * NQ];      // q channels  [b][c][n]
__device__ float g_kvu [BATCH * 2 * DIMC * NU];  // kv upper    [b][c][m]
__device__ float g_kvT [BATCH * NH * NU * 64];   // transposed  [b][h][m][d64] (K:0-31, V:32-63)
__device__ float g_fkv [BATCH * 2 * DIMC * NQ];  // fine kv     [b][c][n]
__device__ float g_qm  [BATCH * DIMC];
__device__ float g_gs  [BATCH * NH * NU];
__device__ int   g_idx [BATCH * NH * 16];
__device__ float g_out [BATCH * DIMC * NQ];
__device__ float g_vpe [BATCH * DIMC * NU];
__device__ ull   g_cacc[BATCH * NH * 16 * NQ];   // unnormalized coarse acc (packed d-pairs)
__device__ float g_esum[BATCH * NH * NQ];        // coarse softmax denominators

// ---------------- f32x2 packed helpers ----------------
__device__ __forceinline__ ull ffma2(ull a, ull b, ull c) {
    ull d; asm("fma.rn.f32x2 %0, %1, %2, %3;" : "=l"(d) : "l"(a), "l"(b), "l"(c)); return d;
}
__device__ __forceinline__ ull fmul2(ull a, ull b) {
    ull d; asm("mul.rn.f32x2 %0, %1, %2;" : "=l"(d) : "l"(a), "l"(b)); return d;
}
__device__ __forceinline__ ull pack2(float lo, float hi) {
    ull r; asm("mov.b64 %0, {%1, %2};" : "=l"(r) : "f"(lo), "f"(hi)); return r;
}
__device__ __forceinline__ float2 unpack2(ull v) {
    float2 f; asm("mov.b64 {%0, %1}, %2;" : "=f"(f.x), "=f"(f.y) : "l"(v)); return f;
}

// ---------------- fast exp2 (scalar, clamped - for fine/gate) ----------------
__device__ __forceinline__ float fexp2(float x) {
    x = fmaxf(fminf(x, 126.0f), -120.0f);
    float z = x + 12582912.0f;
    int   e = __float_as_int(z) - 0x4B400000;
    float f = x - (z - 12582912.0f);
    float p = fmaf(f, 1.3333558146e-3f, 9.6181291918e-3f);
    p = fmaf(f, p, 5.5504108664e-2f);
    p = fmaf(f, p, 2.4022650696e-1f);
    p = fmaf(f, p, 6.9314718056e-1f);
    p = fmaf(f, p, 1.0f);
    return p * __int_as_float((e + 127) << 23);
}

// fast exp2, no clamp (bounded attention scores)
__device__ __forceinline__ float fexp2s(float x) {
    float z = x + 12582912.0f;
    int   e = __float_as_int(z) - 0x4B400000;
    float f = x - (z - 12582912.0f);
    float p = fmaf(f, 1.3333558146e-3f, 9.6181291918e-3f);
    p = fmaf(f, p, 5.5504108664e-2f);
    p = fmaf(f, p, 2.4022650696e-1f);
    p = fmaf(f, p, 6.9314718056e-1f);
    p = fmaf(f, p, 1.0f);
    return p * __int_as_float((e + 127) << 23);
}

// ---------------- threefry2x32 (key = (0, 42)) ----------------
__device__ __forceinline__ uint32_t rotl32(uint32_t v, int n) { return (v << n) | (v >> (32 - n)); }

__device__ __forceinline__ void tf2x32(uint32_t c0, uint32_t c1, uint32_t& o0, uint32_t& o1) {
    const uint32_t k0 = 0u, k1 = 42u, k2 = 0u ^ 42u ^ 0x1BD11BDAu;
    uint32_t x0 = c0 + k0, x1 = c1 + k1;
#define TFR(r) { x0 += x1; x1 = rotl32(x1, r); x1 ^= x0; }
    TFR(13) TFR(15) TFR(26) TFR(6)
    x0 += k1; x1 += k2 + 1u;
    TFR(17) TFR(29) TFR(16) TFR(24)
    x0 += k2; x1 += k0 + 2u;
    TFR(13) TFR(15) TFR(26) TFR(6)
    x0 += k0; x1 += k1 + 3u;
    TFR(17) TFR(29) TFR(16) TFR(24)
    x0 += k1; x1 += k2 + 4u;
    TFR(13) TFR(15) TFR(26) TFR(6)
    x0 += k2; x1 += k0 + 5u;
#undef TFR
    o0 = x0; o1 = x1;
}

// ---------------- GEMM (f32x2): C[M,N] = W[M,256] @ X[256,N] + bias ----------------
__global__ __launch_bounds__(256) void gemm128(const float* __restrict__ W,
                                               const float* __restrict__ X,
                                               const float* __restrict__ bias,
                                               float* __restrict__ C, int M, int N) {
    const int K = DIMC;
    int b = blockIdx.z;
    X += (size_t)b * K * N;
    C += (size_t)b * M * N;
    __shared__ float Ws[8][132];
    __shared__ float Xs[8][128];
    int tid = threadIdx.x;
    int tx = tid & 15, ty = tid >> 4;
    int bm = blockIdx.y * 128, bn = blockIdx.x * 128;

    ull acc2[4][8];
#pragma unroll
    for (int i = 0; i < 4; i++)
#pragma unroll
        for (int j = 0; j < 8; j++) acc2[i][j] = 0ull;

    int wk = tid & 7, wm = tid >> 3;
    int xk = tid >> 7, xn = tid & 127;

    for (int k0 = 0; k0 < K; k0 += 8) {
#pragma unroll
        for (int p = 0; p < 4; p++)
            Ws[wk][wm + p * 32] = W[(size_t)(bm + wm + p * 32) * K + k0 + wk];
#pragma unroll
        for (int p = 0; p < 4; p++)
            Xs[xk + p * 2][xn] = X[(size_t)(k0 + xk + p * 2) * N + bn + xn];
        __syncthreads();
#pragma unroll
        for (int k = 0; k < 8; k++) {
            ull a2[4];
            {
                ulonglong2 t0 = *(const ulonglong2*)&Ws[k][ty * 4];
                ulonglong2 t1 = *(const ulonglong2*)&Ws[k][64 + ty * 4];
                a2[0] = t0.x; a2[1] = t0.y; a2[2] = t1.x; a2[3] = t1.y;
            }
            float bb[8];
            *(float4*)&bb[0] = *(const float4*)&Xs[k][tx * 4];
            *(float4*)&bb[4] = *(const float4*)&Xs[k][64 + tx * 4];
#pragma unroll
            for (int j = 0; j < 8; j++) {
                ull b2 = pack2(bb[j], bb[j]);
#pragma unroll
                for (int i = 0; i < 4; i++) acc2[i][j] = ffma2(a2[i], b2, acc2[i][j]);
            }
        }
        __syncthreads();
    }
#pragma unroll
    for (int i = 0; i < 8; i++) {
        int loc  = (i < 4) ? i : (i - 4);
        int i2   = ((i < 4) ? 0 : 2) + (loc >> 1);
        int half = loc & 1;
        int m = bm + ((i < 4) ? 0 : 64) + ty * 4 + loc;
        float bv = bias[m];
        float v[8];
#pragma unroll
        for (int j = 0; j < 8; j++) {
            float2 u = unpack2(acc2[i2][j]);
            v[j] = (half ? u.y : u.x) + bv;
        }
        *(float4*)&C[(size_t)m * N + bn + tx * 4]      = make_float4(v[0], v[1], v[2], v[3]);
        *(float4*)&C[(size_t)m * N + bn + 64 + tx * 4] = make_float4(v[4], v[5], v[6], v[7]);
    }
}

// ---------------- transpose kv upper: [b][c][m] -> [b][h][m][d64] ----------------
__global__ __launch_bounds__(256) void tr_k() {
    int bh = blockIdx.x >> 4, tile = blockIdx.x & 15;
    int b = bh >> 3, h = bh & 7;
    int m0 = tile * 64;
    __shared__ float s[64][65];
    int t = threadIdx.x;
    const float* src = g_kvu + ((size_t)b * 512 + h * 64) * NU + m0;
#pragma unroll
    for (int i = 0; i < 16; i++) {
        int idx = i * 256 + t;
        int dd = idx >> 6, mm = idx & 63;
        s[dd][mm] = src[(size_t)dd * NU + mm];
    }
    __syncthreads();
    float* dst = g_kvT + ((size_t)bh * NU + m0) * 64;
#pragma unroll
    for (int i = 0; i < 16; i++) {
        int idx = i * 256 + t;
        int mm = idx >> 6, dd = idx & 63;
        dst[mm * 64 + dd] = s[dd][mm];
    }
}

// ---------------- coarse attention: 1 q/thread, LDS.128 float4 + repack to f32x2 ----------------
__global__ __launch_bounds__(128) void coarse_k() {
    __shared__ float KVs[128][64];   // [m][d64]: K cols 0-31, V cols 32-63 (32 KB)

    int bh = blockIdx.y, b = bh >> 3, h = bh & 7;
    int t = threadIdx.x;
    int n = blockIdx.x * 128 + t;
    const float SCL = 0.17677669529663687f * 1.4426950408889634f;

    // load + pre-scale query (packed pairs of adjacent d)
    ull q2[16];
    {
        const float* qb = g_q + ((size_t)b * DIMC + h * HD) * NQ;
#pragma unroll
        for (int p = 0; p < 16; p++)
            q2[p] = pack2(qb[(size_t)(2 * p) * NQ + n] * SCL,
                          qb[(size_t)(2 * p + 1) * NQ + n] * SCL);
    }

    ull acc2[16];
#pragma unroll
    for (int p = 0; p < 16; p++) acc2[p] = 0ull;
    float esum = 0.f;

    const float* kvT = g_kvT + (size_t)bh * NU * 64;

    for (int m0 = 0; m0 < NU; m0 += 128) {
        __syncthreads();
        {
            const float4* src = (const float4*)(kvT + (size_t)m0 * 64);
            float4* dst = (float4*)KVs;
#pragma unroll
            for (int i = 0; i < 16; i++) dst[i * 128 + t] = src[i * 128 + t];
        }
        __syncthreads();
#pragma unroll 1
        for (int m = 0; m < 128; m++) {
            // score: 8 x LDS.128, repacked to f32x2 via mov.b64 (ALU pipe)
            ull s0 = 0ull, s1 = 0ull;
            {
                const float4* kr = (const float4*)&KVs[m][0];
#pragma unroll
                for (int j = 0; j < 8; j++) {
                    float4 kk = kr[j];
                    s0 = ffma2(q2[2 * j],     pack2(kk.x, kk.y), s0);
                    s1 = ffma2(q2[2 * j + 1], pack2(kk.z, kk.w), s1);
                }
            }
            float2 u0 = unpack2(s0), u1 = unpack2(s1);
            float e = fexp2s((u0.x + u0.y) + (u1.x + u1.y));
            esum += e;
            ull e2 = pack2(e, e);
            // accumulate V: 8 x LDS.128 + repack
            {
                const float4* vr = (const float4*)&KVs[m][32];
#pragma unroll
                for (int j = 0; j < 8; j++) {
                    float4 vv = vr[j];
                    acc2[2 * j]     = ffma2(e2, pack2(vv.x, vv.y), acc2[2 * j]);
                    acc2[2 * j + 1] = ffma2(e2, pack2(vv.z, vv.w), acc2[2 * j + 1]);
                }
            }
        }
    }

    ull* cacc = g_cacc + (size_t)bh * 16 * NQ + n;
#pragma unroll
    for (int p = 0; p < 16; p++) cacc[(size_t)p * NQ] = acc2[p];
    g_esum[bh * NQ + n] = esum;
}

// ---------------- mean over n of q channels (float4) ----------------
__global__ void qmean_k() {
    int b = blockIdx.x >> 8, c = blockIdx.x & 255;
    const float4* p = (const float4*)(g_q + ((size_t)b * DIMC + c) * NQ);
    float s = 0.f;
    for (int n = threadIdx.x; n < 1024; n += 256) {
        float4 v = p[n];
        s += (v.x + v.y) + (v.z + v.w);
    }
    __shared__ float sh[8];
    for (int o = 16; o; o >>= 1) s += __shfl_down_sync(0xffffffffu, s, o);
    if ((threadIdx.x & 31) == 0) sh[threadIdx.x >> 5] = s;
    __syncthreads();
    if (threadIdx.x == 0) {
        float t = 0.f;
#pragma unroll
        for (int i = 0; i < 8; i++) t += sh[i];
        g_qm[b * DIMC + c] = t * (1.0f / NQ);
    }
}

// ---------------- global scores + gumbel (float4 reads of transposed K) ----------------
__global__ void gs_k() {
    int j = blockIdx.x * 128 + threadIdx.x;
    int b = j >> 13, r = j & 8191, h = r >> 10, m = r & 1023;
    const float4* qm = (const float4*)(g_qm + b * DIMC + h * HD);
    const float4* kT = (const float4*)(g_kvT + ((size_t)(b * NH + h) * NU + m) * 64);
    float s = 0.f;
#pragma unroll
    for (int i = 0; i < 8; i++) {
        float4 qv = qm[i], kv = kT[i];
        s += qv.x * kv.x + qv.y * kv.y + qv.z * kv.z + qv.w * kv.w;
    }

    uint32_t bits;
#if THREEFRY_PARTITIONABLE
    { uint32_t o0, o1; tf2x32(0u, (uint32_t)j, o0, o1); bits = o0 ^ o1; }
#else
    { uint32_t o0, o1;
      if (j < 8192) { tf2x32((uint32_t)j, (uint32_t)(j + 8192), o0, o1); bits = o0; }
      else          { tf2x32((uint32_t)(j - 8192), (uint32_t)j, o0, o1); bits = o1; } }
#endif
    float f = __uint_as_float((bits >> 9) | 0x3f800000u) - 1.0f;
    const float TINY = 1.1754943508222875e-38f;
    float u = fmaxf(TINY, f + TINY);
    float gum = -logf(-logf(u));
    g_gs[j] = s * 0.17677669529663687f + gum;
}

// ---------------- top-4 per (b,h) + 2x2 expansion ----------------
__global__ void topk_k() {
    int bh = blockIdx.x;
    __shared__ float sv[NU];
    __shared__ float rv[256];
    __shared__ int   ri[256];
    __shared__ int   chosen[4];
    int t = threadIdx.x;
    for (int i = t; i < NU; i += 256) sv[i] = g_gs[bh * NU + i];
    __syncthreads();
    for (int rnd = 0; rnd < 4; rnd++) {
        float bestv = -1e30f; int besti = NU;
        for (int i = t; i < NU; i += 256) {
            float v = sv[i];
            if (v > bestv) { bestv = v; besti = i; }
        }
        rv[t] = bestv; ri[t] = besti;
        __syncthreads();
        for (int o = 128; o; o >>= 1) {
            if (t < o) {
                float v2 = rv[t + o]; int i2 = ri[t + o];
                if (v2 > rv[t] || (v2 == rv[t] && i2 < ri[t])) { rv[t] = v2; ri[t] = i2; }
            }
            __syncthreads();
        }
        if (t == 0) { chosen[rnd] = ri[0]; sv[ri[0]] = -1e30f; }
        __syncthreads();
    }
    if (t < 16) {
        int g = t >> 2, kk = t & 3;
        int dh = g >> 1, dw = g & 1;
        int ti = chosen[kk];
        int hi = (ti >> 5) * 2, wi = (ti & 31) * 2;
        g_idx[bh * 16 + t] = (hi + dh) * 64 + (wi + dw);
    }
}

// ---------------- fine attention + gate (R9 epilogue) ----------------
__global__ __launch_bounds__(128) void fine_k(const float* __restrict__ Wg,
                                              const float* __restrict__ bg) {
    __shared__ ull FKp[16][16];
    __shared__ ull FVp[16][16];
    __shared__ ull Wgp[32][32];
    __shared__ float bgs[32];

    int bh = blockIdx.y, b = bh >> 3, h = bh & 7;
    int t = threadIdx.x;
    int n = blockIdx.x * 128 + t;
    const float SCL = 0.17677669529663687f * 1.4426950408889634f;

    for (int e = t; e < 1024; e += 128) ((ull*)Wgp)[e] = ((const ull*)Wg)[e];
    if (t < 32) bgs[t] = bg[t];
    {
        const int* idxp = g_idx + bh * 16;
        const float* fb = g_fkv + ((size_t)b * 512 + h * 64) * NQ;
        for (int e = t; e < 256; e += 128) {
            int j = e >> 4, p = e & 15;
            int nn = idxp[j];
            FKp[j][p] = pack2(fb[(size_t)(2 * p) * NQ + nn],      fb[(size_t)(2 * p + 1) * NQ + nn]);
            FVp[j][p] = pack2(fb[(size_t)(32 + 2 * p) * NQ + nn], fb[(size_t)(33 + 2 * p) * NQ + nn]);
        }
    }
    __syncthreads();

    // reload query (scaled) and coarse partials
    ull q2[16], acc2[16];
    {
        const float* qb = g_q + ((size_t)b * DIMC + h * HD) * NQ;
#pragma unroll
        for (int p = 0; p < 16; p++)
            q2[p] = pack2(qb[(size_t)(2 * p) * NQ + n] * SCL,
                          qb[(size_t)(2 * p + 1) * NQ + n] * SCL);
        const ull* cacc = g_cacc + (size_t)bh * 16 * NQ + n;
#pragma unroll
        for (int p = 0; p < 16; p++) acc2[p] = cacc[(size_t)p * NQ];
    }
    float esum = g_esum[bh * NQ + n];

    // fine attention weights
    float fe[16]; float fsum = 0.f;
#pragma unroll
    for (int j = 0; j < 16; j++) {
        ull s2 = 0ull;
#pragma unroll
        for (int p = 0; p < 16; p++) s2 = ffma2(q2[p], FKp[j][p], s2);
        float2 u = unpack2(s2);
        float e1 = fexp2(u.x + u.y);
        fe[j] = e1; fsum += e1;
    }
    ull invf2, invc2;
    { float invf = 1.0f / fsum, invc = 1.0f / esum;
      invf2 = pack2(invf, invf); invc2 = pack2(invc, invc); }

    // refined output overwrites q2; coarse scaled in place in acc2
#pragma unroll
    for (int p = 0; p < 16; p++) {
        ull r = 0ull;
#pragma unroll
        for (int j = 0; j < 16; j++) r = ffma2(pack2(fe[j], fe[j]), FVp[j][p], r);
        q2[p]   = fmul2(r, invf2);
        acc2[p] = fmul2(acc2[p], invc2);
    }

    // gate + output
    float* outb = g_out + ((size_t)b * DIMC + h * HD) * NQ + n;
#pragma unroll
    for (int d = 0; d < 32; d++) {
        ull g2 = 0ull;
#pragma unroll
        for (int p = 0; p < 16; p++) {
            g2 = ffma2(acc2[p], Wgp[d][p],      g2);
            g2 = ffma2(q2[p],   Wgp[d][16 + p], g2);
        }
        float2 u = unpack2(g2);
        float s = u.x + u.y + bgs[d];
        float gate = 1.0f / (1.0f + fexp2(-s * 1.4426950408889634f));
        float2 cc = unpack2(acc2[d >> 1]);
        float2 rr = unpack2(q2[d >> 1]);
        float cd = (d & 1) ? cc.y : cc.x;
        float rd = (d & 1) ? rr.y : rr.x;
        outb[(size_t)d * NQ] = cd + gate * (rd - cd);
    }
}

// ---------------- depthwise 7x7 conv on v (32x32 grid) ----------------
__global__ void pe_conv_k(const float* __restrict__ Wpe, const float* __restrict__ bpe) {
    int gid = blockIdx.x * 128 + threadIdx.x;
    int p = gid & 1023, c = (gid >> 10) & 255, b = gid >> 18;
    int y = p >> 5, x = p & 31;
    int h = c >> 5, d = c & 31;
    const float* vsrc = g_kvu + ((size_t)b * 512 + h * 64 + 32 + d) * NU;
    const float* w = Wpe + c * 49;
    float s = bpe[c];
#pragma unroll
    for (int ky = 0; ky < 7; ky++) {
        int iy = y + ky - 3;
        if ((unsigned)iy < 32u) {
#pragma unroll
            for (int kx = 0; kx < 7; kx++) {
                int ix = x + kx - 3;
                if ((unsigned)ix < 32u) s = fmaf(vsrc[iy * 32 + ix], w[ky * 7 + kx], s);
            }
        }
    }
    g_vpe[gid] = s;
}

// ---------------- bilinear 2x upsample + add ----------------
__global__ void upadd_k() {
    int gid = blockIdx.x * 256 + threadIdx.x;
    int n = gid & 4095, c = (gid >> 12) & 255, b = gid >> 20;
    int y = n >> 6, x = n & 63;
    float fy = (y + 0.5f) * 0.5f - 0.5f;
    float fx = (x + 0.5f) * 0.5f - 0.5f;
    float yf = floorf(fy), xf = floorf(fx);
    float ty = fy - yf, tx = fx - xf;
    int y0 = max(0, min(31, (int)yf)),     y1 = max(0, min(31, (int)yf + 1));
    int x0 = max(0, min(31, (int)xf)),     x1 = max(0, min(31, (int)xf + 1));
    const float* src = g_vpe + ((size_t)b * 256 + c) * NU;
    float v = (1.f - ty) * ((1.f - tx) * src[y0 * 32 + x0] + tx * src[y0 * 32 + x1])
            +        ty  * ((1.f - tx) * src[y1 * 32 + x0] + tx * src[y1 * 32 + x1]);
    g_out[gid] += v;
}

// ---------------- launch ----------------
extern "C" void kernel_launch(void* const* d_in, const int* in_sizes, int n_in,
                              void* d_out, int out_size) {
    const float* x     = (const float*)d_in[0];
    const float* uf    = (const float*)d_in[1];
    const float* Wq    = (const float*)d_in[2];
    const float* bq    = (const float*)d_in[3];
    const float* Wkv   = (const float*)d_in[4];
    const float* bkv   = (const float*)d_in[5];
    const float* Wproj = (const float*)d_in[6];
    const float* bproj = (const float*)d_in[7];
    const float* Wpe   = (const float*)d_in[8];
    const float* bpe   = (const float*)d_in[9];
    const float* Wg    = (const float*)d_in[10];
    const float* bg    = (const float*)d_in[11];
    float* out = (float*)d_out;

    float *pq, *pkvu, *pfkv, *pout;
    cudaGetSymbolAddress((void**)&pq,   g_q);
    cudaGetSymbolAddress((void**)&pkvu, g_kvu);
    cudaGetSymbolAddress((void**)&pfkv, g_fkv);
    cudaGetSymbolAddress((void**)&pout, g_out);

    gemm128<<<dim3(32, 2, 2), 256>>>(Wq,  x,  bq,  pq,   256, 4096);   // 1
    gemm128<<<dim3(8,  4, 2), 256>>>(Wkv, uf, bkv, pkvu, 512, 1024);   // 2
    tr_k<<<256, 256>>>();                                              // 3
    coarse_k<<<dim3(32, 16), 128>>>();                                 // 4 -> ncu slot
    gemm128<<<dim3(32, 4, 2), 256>>>(Wkv, x,  bkv, pfkv, 512, 4096);   // 5
    qmean_k<<<512, 256>>>();                                           // 6
    gs_k<<<128, 128>>>();                                              // 7
    topk_k<<<16, 256>>>();                                             // 8
    fine_k<<<dim3(32, 16), 128>>>(Wg, bg);                             // 9
    pe_conv_k<<<4096, 128>>>(Wpe, bpe);                                // 10
    upadd_k<<<8192, 256>>>();                                          // 11
    gemm128<<<dim3(32, 2, 2), 256>>>(Wproj, pout, bproj, out, 256, 4096); // 12
}

// round 17
// speedup vs baseline: 1.6635x; 1.0908x over previous
#include <cuda_runtime.h>
#include <cstdint>
#include <cstddef>

#define DIMC 256
#define NH 8
#define HD 32
#define NQ 4096
#define NU 1024
#define BATCH 2

#define THREEFRY_PARTITIONABLE 1

typedef unsigned long long ull;

// ---------------- scratch (device globals; no allocation) ----------------
__device__ float g_q   [BATCH * DIMC * NQ];      // q channels  [b][c][n]
__device__ float g_kvu [BATCH * 2 * DIMC * NU];  // kv upper    [b][c][m]
__device__ float g_kvT [BATCH * NH * NU * 64];   // transposed  [b][h][m][d64] (K:0-31, V:32-63)
__device__ float g_fkv [BATCH * 2 * DIMC * NQ];  // fine kv     [b][c][n]
__device__ float g_qm  [BATCH * DIMC];
__device__ float g_gs  [BATCH * NH * NU];
__device__ int   g_idx [BATCH * NH * 16];
__device__ float g_out [BATCH * DIMC * NQ];
__device__ float g_vpe [BATCH * DIMC * NU];
__device__ ull   g_cacc[BATCH * NH * 16 * NQ];   // unnormalized coarse acc (packed d-pairs)
__device__ float g_esum[BATCH * NH * NQ];        // coarse softmax denominators

// ---------------- f32x2 packed helpers ----------------
__device__ __forceinline__ ull ffma2(ull a, ull b, ull c) {
    ull d; asm("fma.rn.f32x2 %0, %1, %2, %3;" : "=l"(d) : "l"(a), "l"(b), "l"(c)); return d;
}
__device__ __forceinline__ ull fmul2(ull a, ull b) {
    ull d; asm("mul.rn.f32x2 %0, %1, %2;" : "=l"(d) : "l"(a), "l"(b)); return d;
}
__device__ __forceinline__ ull pack2(float lo, float hi) {
    ull r; asm("mov.b64 %0, {%1, %2};" : "=l"(r) : "f"(lo), "f"(hi)); return r;
}
__device__ __forceinline__ float2 unpack2(ull v) {
    float2 f; asm("mov.b64 {%0, %1}, %2;" : "=f"(f.x), "=f"(f.y) : "l"(v)); return f;
}

// ---------------- fast exp2 (scalar, clamped - for fine/gate) ----------------
__device__ __forceinline__ float fexp2(float x) {
    x = fmaxf(fminf(x, 126.0f), -120.0f);
    float z = x + 12582912.0f;
    int   e = __float_as_int(z) - 0x4B400000;
    float f = x - (z - 12582912.0f);
    float p = fmaf(f, 1.3333558146e-3f, 9.6181291918e-3f);
    p = fmaf(f, p, 5.5504108664e-2f);
    p = fmaf(f, p, 2.4022650696e-1f);
    p = fmaf(f, p, 6.9314718056e-1f);
    p = fmaf(f, p, 1.0f);
    return p * __int_as_float((e + 127) << 23);
}

// packed exp2 of two scores (inputs bounded, no clamp needed)
__device__ __forceinline__ ull fexp2_2(float x0, float x1) {
    float z0 = x0 + 12582912.0f, z1 = x1 + 12582912.0f;
    int e0 = __float_as_int(z0) - 0x4B400000;
    int e1 = __float_as_int(z1) - 0x4B400000;
    float f0 = x0 - (z0 - 12582912.0f);
    float f1 = x1 - (z1 - 12582912.0f);
    ull f2 = pack2(f0, f1);
    ull p  = pack2(1.3333558146e-3f, 1.3333558146e-3f);
    p = ffma2(f2, p, pack2(9.6181291918e-3f, 9.6181291918e-3f));
    p = ffma2(f2, p, pack2(5.5504108664e-2f, 5.5504108664e-2f));
    p = ffma2(f2, p, pack2(2.4022650696e-1f, 2.4022650696e-1f));
    p = ffma2(f2, p, pack2(6.9314718056e-1f, 6.9314718056e-1f));
    p = ffma2(f2, p, pack2(1.0f, 1.0f));
    ull sc = pack2(__int_as_float((e0 + 127) << 23), __int_as_float((e1 + 127) << 23));
    return fmul2(p, sc);
}

// ---------------- threefry2x32 (key = (0, 42)) ----------------
__device__ __forceinline__ uint32_t rotl32(uint32_t v, int n) { return (v << n) | (v >> (32 - n)); }

__device__ __forceinline__ void tf2x32(uint32_t c0, uint32_t c1, uint32_t& o0, uint32_t& o1) {
    const uint32_t k0 = 0u, k1 = 42u, k2 = 0u ^ 42u ^ 0x1BD11BDAu;
    uint32_t x0 = c0 + k0, x1 = c1 + k1;
#define TFR(r) { x0 += x1; x1 = rotl32(x1, r); x1 ^= x0; }
    TFR(13) TFR(15) TFR(26) TFR(6)
    x0 += k1; x1 += k2 + 1u;
    TFR(17) TFR(29) TFR(16) TFR(24)
    x0 += k2; x1 += k0 + 2u;
    TFR(13) TFR(15) TFR(26) TFR(6)
    x0 += k0; x1 += k1 + 3u;
    TFR(17) TFR(29) TFR(16) TFR(24)
    x0 += k1; x1 += k2 + 4u;
    TFR(13) TFR(15) TFR(26) TFR(6)
    x0 += k2; x1 += k0 + 5u;
#undef TFR
    o0 = x0; o1 = x1;
}

// ---------------- GEMM (f32x2): C[M,N] = W[M,256] @ X[256,N] + bias ----------------
__global__ __launch_bounds__(256) void gemm128(const float* __restrict__ W,
                                               const float* __restrict__ X,
                                               const float* __restrict__ bias,
                                               float* __restrict__ C, int M, int N) {
    const int K = DIMC;
    int b = blockIdx.z;
    X += (size_t)b * K * N;
    C += (size_t)b * M * N;
    __shared__ float Ws[8][132];
    __shared__ float Xs[8][128];
    int tid = threadIdx.x;
    int tx = tid & 15, ty = tid >> 4;
    int bm = blockIdx.y * 128, bn = blockIdx.x * 128;

    ull acc2[4][8];
#pragma unroll
    for (int i = 0; i < 4; i++)
#pragma unroll
        for (int j = 0; j < 8; j++) acc2[i][j] = 0ull;

    int wk = tid & 7, wm = tid >> 3;
    int xk = tid >> 7, xn = tid & 127;

    for (int k0 = 0; k0 < K; k0 += 8) {
#pragma unroll
        for (int p = 0; p < 4; p++)
            Ws[wk][wm + p * 32] = W[(size_t)(bm + wm + p * 32) * K + k0 + wk];
#pragma unroll
        for (int p = 0; p < 4; p++)
            Xs[xk + p * 2][xn] = X[(size_t)(k0 + xk + p * 2) * N + bn + xn];
        __syncthreads();
#pragma unroll
        for (int k = 0; k < 8; k++) {
            ull a2[4];
            {
                ulonglong2 t0 = *(const ulonglong2*)&Ws[k][ty * 4];
                ulonglong2 t1 = *(const ulonglong2*)&Ws[k][64 + ty * 4];
                a2[0] = t0.x; a2[1] = t0.y; a2[2] = t1.x; a2[3] = t1.y;
            }
            float bb[8];
            *(float4*)&bb[0] = *(const float4*)&Xs[k][tx * 4];
            *(float4*)&bb[4] = *(const float4*)&Xs[k][64 + tx * 4];
#pragma unroll
            for (int j = 0; j < 8; j++) {
                ull b2 = pack2(bb[j], bb[j]);
#pragma unroll
                for (int i = 0; i < 4; i++) acc2[i][j] = ffma2(a2[i], b2, acc2[i][j]);
            }
        }
        __syncthreads();
    }
#pragma unroll
    for (int i = 0; i < 8; i++) {
        int loc  = (i < 4) ? i : (i - 4);
        int i2   = ((i < 4) ? 0 : 2) + (loc >> 1);
        int half = loc & 1;
        int m = bm + ((i < 4) ? 0 : 64) + ty * 4 + loc;
        float bv = bias[m];
        float v[8];
#pragma unroll
        for (int j = 0; j < 8; j++) {
            float2 u = unpack2(acc2[i2][j]);
            v[j] = (half ? u.y : u.x) + bv;
        }
        *(float4*)&C[(size_t)m * N + bn + tx * 4]      = make_float4(v[0], v[1], v[2], v[3]);
        *(float4*)&C[(size_t)m * N + bn + 64 + tx * 4] = make_float4(v[4], v[5], v[6], v[7]);
    }
}

// ---------------- transpose kv upper: [b][c][m] -> [b][h][m][d64] ----------------
__global__ __launch_bounds__(256) void tr_k() {
    int bh = blockIdx.x >> 4, tile = blockIdx.x & 15;
    int b = bh >> 3, h = bh & 7;
    int m0 = tile * 64;
    __shared__ float s[64][65];
    int t = threadIdx.x;
    const float* src = g_kvu + ((size_t)b * 512 + h * 64) * NU + m0;
#pragma unroll
    for (int i = 0; i < 16; i++) {
        int idx = i * 256 + t;
        int dd = idx >> 6, mm = idx & 63;
        s[dd][mm] = src[(size_t)dd * NU + mm];
    }
    __syncthreads();
    float* dst = g_kvT + ((size_t)bh * NU + m0) * 64;
#pragma unroll
    for (int i = 0; i < 16; i++) {
        int idx = i * 256 + t;
        int mm = idx >> 6, dd = idx & 63;
        dst[mm * 64 + dd] = s[dd][mm];
    }
}

// ---------------- coarse attention: 2 queries/thread, no epilogue (split) ----------------
__global__ __launch_bounds__(128) void coarse_k() {
    __shared__ float KVs[128][64];   // [m][d64]: K cols 0-31, V cols 32-63 (32 KB)

    int bh = blockIdx.y, b = bh >> 3, h = bh & 7;
    int t = threadIdx.x;
    int n0 = blockIdx.x * 256 + t;   // second query at n0 + 128
    const float SCL = 0.17677669529663687f * 1.4426950408889634f;

    // load + pre-scale both queries (packed pairs of adjacent d)
    ull qa[16], qb[16];
    {
        const float* qp = g_q + ((size_t)b * DIMC + h * HD) * NQ;
#pragma unroll
        for (int p = 0; p < 16; p++) {
            qa[p] = pack2(qp[(size_t)(2 * p) * NQ + n0] * SCL,
                          qp[(size_t)(2 * p + 1) * NQ + n0] * SCL);
            qb[p] = pack2(qp[(size_t)(2 * p) * NQ + n0 + 128] * SCL,
                          qp[(size_t)(2 * p + 1) * NQ + n0 + 128] * SCL);
        }
    }

    ull aa[16], ab[16];
#pragma unroll
    for (int p = 0; p < 16; p++) { aa[p] = 0ull; ab[p] = 0ull; }
    float esa = 0.f, esb = 0.f;

    const float* kvT = g_kvT + (size_t)bh * NU * 64;

    for (int m0 = 0; m0 < NU; m0 += 128) {
        __syncthreads();
        {
            const float4* src = (const float4*)(kvT + (size_t)m0 * 64);
            float4* dst = (float4*)KVs;
#pragma unroll
            for (int i = 0; i < 16; i++) dst[i * 128 + t] = src[i * 128 + t];
        }
        __syncthreads();
#pragma unroll 1
        for (int m = 0; m < 128; m++) {
            // scores for both queries off the same K broadcast
            ull sa0 = 0ull, sa1 = 0ull, sb0 = 0ull, sb1 = 0ull;
            {
                const float4* kr = (const float4*)&KVs[m][0];
#pragma unroll
                for (int j = 0; j < 8; j++) {
                    float4 kk = kr[j];
                    ull k0 = pack2(kk.x, kk.y);
                    ull k1 = pack2(kk.z, kk.w);
                    sa0 = ffma2(qa[2 * j],     k0, sa0);
                    sa1 = ffma2(qa[2 * j + 1], k1, sa1);
                    sb0 = ffma2(qb[2 * j],     k0, sb0);
                    sb1 = ffma2(qb[2 * j + 1], k1, sb1);
                }
            }
            float2 ua0 = unpack2(sa0), ua1 = unpack2(sa1);
            float2 ub0 = unpack2(sb0), ub1 = unpack2(sb1);
            float sA = (ua0.x + ua0.y) + (ua1.x + ua1.y);
            float sB = (ub0.x + ub0.y) + (ub1.x + ub1.y);
            float2 ee = unpack2(fexp2_2(sA, sB));
            esa += ee.x; esb += ee.y;
            ull eA = pack2(ee.x, ee.x), eB = pack2(ee.y, ee.y);
            // accumulate V for both queries off the same V broadcast
            {
                const float4* vr = (const float4*)&KVs[m][32];
#pragma unroll
                for (int j = 0; j < 8; j++) {
                    float4 vv = vr[j];
                    ull v0 = pack2(vv.x, vv.y);
                    ull v1 = pack2(vv.z, vv.w);
                    aa[2 * j]     = ffma2(eA, v0, aa[2 * j]);
                    aa[2 * j + 1] = ffma2(eA, v1, aa[2 * j + 1]);
                    ab[2 * j]     = ffma2(eB, v0, ab[2 * j]);
                    ab[2 * j + 1] = ffma2(eB, v1, ab[2 * j + 1]);
                }
            }
        }
    }

    ull* cacc = g_cacc + (size_t)bh * 16 * NQ;
#pragma unroll
    for (int p = 0; p < 16; p++) {
        cacc[(size_t)p * NQ + n0]       = aa[p];
        cacc[(size_t)p * NQ + n0 + 128] = ab[p];
    }
    g_esum[bh * NQ + n0]       = esa;
    g_esum[bh * NQ + n0 + 128] = esb;
}

// ---------------- mean over n of q channels (float4) ----------------
__global__ void qmean_k() {
    int b = blockIdx.x >> 8, c = blockIdx.x & 255;
    const float4* p = (const float4*)(g_q + ((size_t)b * DIMC + c) * NQ);
    float s = 0.f;
    for (int n = threadIdx.x; n < 1024; n += 256) {
        float4 v = p[n];
        s += (v.x + v.y) + (v.z + v.w);
    }
    __shared__ float sh[8];
    for (int o = 16; o; o >>= 1) s += __shfl_down_sync(0xffffffffu, s, o);
    if ((threadIdx.x & 31) == 0) sh[threadIdx.x >> 5] = s;
    __syncthreads();
    if (threadIdx.x == 0) {
        float t = 0.f;
#pragma unroll
        for (int i = 0; i < 8; i++) t += sh[i];
        g_qm[b * DIMC + c] = t * (1.0f / NQ);
    }
}

// ---------------- global scores + gumbel (float4 reads of transposed K) ----------------
__global__ void gs_k() {
    int j = blockIdx.x * 128 + threadIdx.x;
    int b = j >> 13, r = j & 8191, h = r >> 10, m = r & 1023;
    const float4* qm = (const float4*)(g_qm + b * DIMC + h * HD);
    const float4* kT = (const float4*)(g_kvT + ((size_t)(b * NH + h) * NU + m) * 64);
    float s = 0.f;
#pragma unroll
    for (int i = 0; i < 8; i++) {
        float4 qv = qm[i], kv = kT[i];
        s += qv.x * kv.x + qv.y * kv.y + qv.z * kv.z + qv.w * kv.w;
    }

    uint32_t bits;
#if THREEFRY_PARTITIONABLE
    { uint32_t o0, o1; tf2x32(0u, (uint32_t)j, o0, o1); bits = o0 ^ o1; }
#else
    { uint32_t o0, o1;
      if (j < 8192) { tf2x32((uint32_t)j, (uint32_t)(j + 8192), o0, o1); bits = o0; }
      else          { tf2x32((uint32_t)(j - 8192), (uint32_t)j, o0, o1); bits = o1; } }
#endif
    float f = __uint_as_float((bits >> 9) | 0x3f800000u) - 1.0f;
    const float TINY = 1.1754943508222875e-38f;
    float u = fmaxf(TINY, f + TINY);
    float gum = -logf(-logf(u));
    g_gs[j] = s * 0.17677669529663687f + gum;
}

// ---------------- top-4 per (b,h) + 2x2 expansion ----------------
__global__ void topk_k() {
    int bh = blockIdx.x;
    __shared__ float sv[NU];
    __shared__ float rv[256];
    __shared__ int   ri[256];
    __shared__ int   chosen[4];
    int t = threadIdx.x;
    for (int i = t; i < NU; i += 256) sv[i] = g_gs[bh * NU + i];
    __syncthreads();
    for (int rnd = 0; rnd < 4; rnd++) {
        float bestv = -1e30f; int besti = NU;
        for (int i = t; i < NU; i += 256) {
            float v = sv[i];
            if (v > bestv) { bestv = v; besti = i; }
        }
        rv[t] = bestv; ri[t] = besti;
        __syncthreads();
        for (int o = 128; o; o >>= 1) {
            if (t < o) {
                float v2 = rv[t + o]; int i2 = ri[t + o];
                if (v2 > rv[t] || (v2 == rv[t] && i2 < ri[t])) { rv[t] = v2; ri[t] = i2; }
            }
            __syncthreads();
        }
        if (t == 0) { chosen[rnd] = ri[0]; sv[ri[0]] = -1e30f; }
        __syncthreads();
    }
    if (t < 16) {
        int g = t >> 2, kk = t & 3;
        int dh = g >> 1, dw = g & 1;
        int ti = chosen[kk];
        int hi = (ti >> 5) * 2, wi = (ti & 31) * 2;
        g_idx[bh * 16 + t] = (hi + dh) * 64 + (wi + dw);
    }
}

// ---------------- fine attention + gate ----------------
__global__ __launch_bounds__(128) void fine_k(const float* __restrict__ Wg,
                                              const float* __restrict__ bg) {
    __shared__ ull FKp[16][16];
    __shared__ ull FVp[16][16];
    __shared__ ull Wgp[32][32];
    __shared__ float bgs[32];

    int bh = blockIdx.y, b = bh >> 3, h = bh & 7;
    int t = threadIdx.x;
    int n = blockIdx.x * 128 + t;
    const float SCL = 0.17677669529663687f * 1.4426950408889634f;

    for (int e = t; e < 1024; e += 128) ((ull*)Wgp)[e] = ((const ull*)Wg)[e];
    if (t < 32) bgs[t] = bg[t];
    {
        const int* idxp = g_idx + bh * 16;
        const float* fb = g_fkv + ((size_t)b * 512 + h * 64) * NQ;
        for (int e = t; e < 256; e += 128) {
            int j = e >> 4, p = e & 15;
            int nn = idxp[j];
            FKp[j][p] = pack2(fb[(size_t)(2 * p) * NQ + nn],      fb[(size_t)(2 * p + 1) * NQ + nn]);
            FVp[j][p] = pack2(fb[(size_t)(32 + 2 * p) * NQ + nn], fb[(size_t)(33 + 2 * p) * NQ + nn]);
        }
    }
    __syncthreads();

    // reload query (scaled) and coarse partials
    ull q2[16], acc2[16];
    {
        const float* qb = g_q + ((size_t)b * DIMC + h * HD) * NQ;
#pragma unroll
        for (int p = 0; p < 16; p++)
            q2[p] = pack2(qb[(size_t)(2 * p) * NQ + n] * SCL,
                          qb[(size_t)(2 * p + 1) * NQ + n] * SCL);
        const ull* cacc = g_cacc + (size_t)bh * 16 * NQ + n;
#pragma unroll
        for (int p = 0; p < 16; p++) acc2[p] = cacc[(size_t)p * NQ];
    }
    float esum = g_esum[bh * NQ + n];

    // fine attention weights
    float fe[16]; float fsum = 0.f;
#pragma unroll
    for (int j = 0; j < 16; j++) {
        ull s2 = 0ull;
#pragma unroll
        for (int p = 0; p < 16; p++) s2 = ffma2(q2[p], FKp[j][p], s2);
        float2 u = unpack2(s2);
        float e1 = fexp2(u.x + u.y);
        fe[j] = e1; fsum += e1;
    }
    ull invf2, invc2;
    { float invf = 1.0f / fsum, invc = 1.0f / esum;
      invf2 = pack2(invf, invf); invc2 = pack2(invc, invc); }

    // refined output overwrites q2; coarse scaled in place in acc2
#pragma unroll
    for (int p = 0; p < 16; p++) {
        ull r = 0ull;
#pragma unroll
        for (int j = 0; j < 16; j++) r = ffma2(pack2(fe[j], fe[j]), FVp[j][p], r);
        q2[p]   = fmul2(r, invf2);
        acc2[p] = fmul2(acc2[p], invc2);
    }

    // gate + output
    float* outb = g_out + ((size_t)b * DIMC + h * HD) * NQ + n;
#pragma unroll
    for (int d = 0; d < 32; d++) {
        ull g2 = 0ull;
#pragma unroll
        for (int p = 0; p < 16; p++) {
            g2 = ffma2(acc2[p], Wgp[d][p],      g2);
            g2 = ffma2(q2[p],   Wgp[d][16 + p], g2);
        }
        float2 u = unpack2(g2);
        float s = u.x + u.y + bgs[d];
        float gate = 1.0f / (1.0f + fexp2(-s * 1.4426950408889634f));
        float2 cc = unpack2(acc2[d >> 1]);
        float2 rr = unpack2(q2[d >> 1]);
        float cd = (d & 1) ? cc.y : cc.x;
        float rd = (d & 1) ? rr.y : rr.x;
        outb[(size_t)d * NQ] = cd + gate * (rd - cd);
    }
}

// ---------------- depthwise 7x7 conv on v (32x32 grid) ----------------
__global__ void pe_conv_k(const float* __restrict__ Wpe, const float* __restrict__ bpe) {
    int gid = blockIdx.x * 128 + threadIdx.x;
    int p = gid & 1023, c = (gid >> 10) & 255, b = gid >> 18;
    int y = p >> 5, x = p & 31;
    int h = c >> 5, d = c & 31;
    const float* vsrc = g_kvu + ((size_t)b * 512 + h * 64 + 32 + d) * NU;
    const float* w = Wpe + c * 49;
    float s = bpe[c];
#pragma unroll
    for (int ky = 0; ky < 7; ky++) {
        int iy = y + ky - 3;
        if ((unsigned)iy < 32u) {
#pragma unroll
            for (int kx = 0; kx < 7; kx++) {
                int ix = x + kx - 3;
                if ((unsigned)ix < 32u) s = fmaf(vsrc[iy * 32 + ix], w[ky * 7 + kx], s);
            }
        }
    }
    g_vpe[gid] = s;
}

// ---------------- bilinear 2x upsample + add ----------------
__global__ void upadd_k() {
    int gid = blockIdx.x * 256 + threadIdx.x;
    int n = gid & 4095, c = (gid >> 12) & 255, b = gid >> 20;
    int y = n >> 6, x = n & 63;
    float fy = (y + 0.5f) * 0.5f - 0.5f;
    float fx = (x + 0.5f) * 0.5f - 0.5f;
    float yf = floorf(fy), xf = floorf(fx);
    float ty = fy - yf, tx = fx - xf;
    int y0 = max(0, min(31, (int)yf)),     y1 = max(0, min(31, (int)yf + 1));
    int x0 = max(0, min(31, (int)xf)),     x1 = max(0, min(31, (int)xf + 1));
    const float* src = g_vpe + ((size_t)b * 256 + c) * NU;
    float v = (1.f - ty) * ((1.f - tx) * src[y0 * 32 + x0] + tx * src[y0 * 32 + x1])
            +        ty  * ((1.f - tx) * src[y1 * 32 + x0] + tx * src[y1 * 32 + x1]);
    g_out[gid] += v;
}

// ---------------- launch ----------------
extern "C" void kernel_launch(void* const* d_in, const int* in_sizes, int n_in,
                              void* d_out, int out_size) {
    const float* x     = (const float*)d_in[0];
    const float* uf    = (const float*)d_in[1];
    const float* Wq    = (const float*)d_in[2];
    const float* bq    = (const float*)d_in[3];
    const float* Wkv   = (const float*)d_in[4];
    const float* bkv   = (const float*)d_in[5];
    const float* Wproj = (const float*)d_in[6];
    const float* bproj = (const float*)d_in[7];
    const float* Wpe   = (const float*)d_in[8];
    const float* bpe   = (const float*)d_in[9];
    const float* Wg    = (const float*)d_in[10];
    const float* bg    = (const float*)d_in[11];
    float* out = (float*)d_out;

    float *pq, *pkvu, *pfkv, *pout;
    cudaGetSymbolAddress((void**)&pq,   g_q);
    cudaGetSymbolAddress((void**)&pkvu, g_kvu);
    cudaGetSymbolAddress((void**)&pfkv, g_fkv);
    cudaGetSymbolAddress((void**)&pout, g_out);

    gemm128<<<dim3(32, 2, 2), 256>>>(Wq,  x,  bq,  pq,   256, 4096);   // 1
    gemm128<<<dim3(8,  4, 2), 256>>>(Wkv, uf, bkv, pkvu, 512, 1024);   // 2
    tr_k<<<256, 256>>>();                                              // 3
    coarse_k<<<dim3(16, 16), 128>>>();                                 // 4 -> ncu slot
    gemm128<<<dim3(32, 4, 2), 256>>>(Wkv, x,  bkv, pfkv, 512, 4096);   // 5
    qmean_k<<<512, 256>>>();                                           // 6
    gs_k<<<128, 128>>>();                                              // 7
    topk_k<<<16, 256>>>();                                             // 8
    fine_k<<<dim3(32, 16), 128>>>(Wg, bg);                             // 9
    pe_conv_k<<<4096, 128>>>(Wpe, bpe);                                // 10
    upadd_k<<<8192, 256>>>();                                          // 11
    gemm128<<<dim3(32, 2, 2), 256>>>(Wproj, pout, bproj, out, 256, 4096); // 12
}